// round 10
// baseline (speedup 1.0000x reference)
#include <cuda_runtime.h>
#include <cstddef>

#define D_DIM   64
#define N_USERS 4096
#define N_ITEMS 16384
#define L_U     50
#define L_I     20
#define OUT_W   (D_DIM + 2)   // 66
#define N_ROWS  (N_USERS + N_ITEMS)
#define WPB     5             // 1 user warp + 4 item warps => uniform blocks

// Core accumulation for one row. Lane l owns columns 2l, 2l+1.
template <int L, bool IS_USER>
__device__ __forceinline__
void do_row(const float* __restrict__ emb,
            const float* __restrict__ w,
            float                     bias,
            const float* __restrict__ h1,
            const int*   __restrict__ my_idx,
            float*       __restrict__ orow,
            int lane)
{
    int idx_lo = (L >= 32 || lane < L) ? my_idx[lane] : 0;
    int idx_hi = 0;
    if (L > 32) idx_hi = (lane + 32 < L) ? my_idx[lane + 32] : 0;

    float wsum = 0.f;
    if (L >= 32 || lane < L) wsum += __ldg(&w[idx_lo]);
    if (L > 32 && lane + 32 < L) wsum += __ldg(&w[idx_hi]);

    float sx = 0.f, sy = 0.f, qx = 0.f, qy = 0.f;

    #pragma unroll
    for (int j = 0; j < L; ++j) {
        int src = (L <= 32 || j < 32) ? idx_lo : idx_hi;
        int r   = __shfl_sync(0xffffffffu, src, j & 31);
        float2 g = *reinterpret_cast<const float2*>(emb + (size_t)r * D_DIM + 2 * lane);
        sx += g.x; sy += g.y;
        qx += g.x * g.x; qy += g.y * g.y;
    }

    float2 h = *reinterpret_cast<const float2*>(h1 + 2 * lane);
    float part = 0.5f * (sx * sx - qx) * h.x
               + 0.5f * (sy * sy - qy) * h.y + wsum;

    #pragma unroll
    for (int o = 16; o > 0; o >>= 1)
        part += __shfl_xor_sync(0xffffffffu, part, o);

    float2 sv; sv.x = sx; sv.y = sy;
    *reinterpret_cast<float2*>(orow + 2 * lane) = sv;  // stride 66 even -> 8B aligned

    if (lane == 0) {
        if (IS_USER) {
            orow[D_DIM]     = part + bias;
            orow[D_DIM + 1] = 1.0f;
        } else {
            orow[D_DIM]     = 1.0f;
            orow[D_DIM + 1] = part;
        }
    }
}

// Uniform-duration blocks: block b = {user row b} + {item rows 4b..4b+3}.
// Every block does exactly 130 gathers; 4096 identical blocks, 20480 warps.
__global__ __launch_bounds__(WPB * 32)
void fm_uniform_kernel(const float* __restrict__ uemb,
                       const float* __restrict__ iemb,
                       const float* __restrict__ uw,
                       const float* __restrict__ iw,
                       const float* __restrict__ gbias,
                       const float* __restrict__ h1,
                       const float* __restrict__ h2,
                       const int*   __restrict__ uidx,
                       const int*   __restrict__ iidx,
                       float*       __restrict__ out)
{
    const int lane = threadIdx.x & 31;
    const int wib  = threadIdx.x >> 5;      // 0..4
    const int b    = blockIdx.x;            // 0..4095

    if (b == 0 && threadIdx.x < D_DIM) {
        out[(size_t)N_ROWS * OUT_W + threadIdx.x] = h2[threadIdx.x];
    }

    if (wib == 0) {
        // user row b
        do_row<L_U, true>(uemb, uw, gbias[0], h1,
                          uidx + (size_t)b * L_U,
                          out + (size_t)b * OUT_W, lane);
    } else {
        // item row 4b + (wib-1)
        const int row = 4 * b + (wib - 1);
        do_row<L_I, false>(iemb, iw, 0.f, h1,
                           iidx + (size_t)row * L_I,
                           out + (size_t)(N_USERS + row) * OUT_W, lane);
    }
}

extern "C" void kernel_launch(void* const* d_in, const int* in_sizes, int n_in,
                              void* d_out, int out_size)
{
    const float* uemb  = (const float*)d_in[0];
    const float* iemb  = (const float*)d_in[1];
    const float* uw    = (const float*)d_in[2];
    const float* iw    = (const float*)d_in[3];
    const float* gbias = (const float*)d_in[4];
    const float* h1    = (const float*)d_in[5];
    const float* h2    = (const float*)d_in[6];
    const int*   uidx  = (const int*)d_in[7];
    const int*   iidx  = (const int*)d_in[8];

    float* out = (float*)d_out;

    fm_uniform_kernel<<<N_USERS, WPB * 32>>>(uemb, iemb, uw, iw, gbias, h1, h2,
                                             uidx, iidx, out);
}

// round 11
// speedup vs baseline: 1.0052x; 1.0052x over previous
#include <cuda_runtime.h>
#include <cstddef>

#define D_DIM   64
#define N_USERS 4096
#define N_ITEMS 16384
#define L_U     50
#define L_I     20
#define OUT_W   (D_DIM + 2)   // 66
#define N_ROWS  (N_USERS + N_ITEMS)
#define N_WARPS 20480         // 4096*5: warp g -> user g/5 if g%5==0 else item

// .cg load: cache in L2, bypass L1 (0% L1 hit rate on random gathers)
__device__ __forceinline__ float2 ldcg_f2(const float* p) {
    float2 v;
    asm volatile("ld.global.cg.v2.f32 {%0, %1}, [%2];"
                 : "=f"(v.x), "=f"(v.y) : "l"(p));
    return v;
}

// Core accumulation for one row. Lane l owns columns 2l, 2l+1.
template <int L, bool IS_USER>
__device__ __forceinline__
void do_row(const float* __restrict__ emb,
            const float* __restrict__ w,
            float                     bias,
            const float* __restrict__ h1,
            const int*   __restrict__ my_idx,
            float*       __restrict__ orow,
            int lane)
{
    int idx_lo = (L >= 32 || lane < L) ? my_idx[lane] : 0;
    int idx_hi = 0;
    if (L > 32) idx_hi = (lane + 32 < L) ? my_idx[lane + 32] : 0;

    float wsum = 0.f;
    if (L >= 32 || lane < L) wsum += __ldg(&w[idx_lo]);
    if (L > 32 && lane + 32 < L) wsum += __ldg(&w[idx_hi]);

    float sx = 0.f, sy = 0.f, qx = 0.f, qy = 0.f;

    #pragma unroll
    for (int j = 0; j < L; ++j) {
        int src = (L <= 32 || j < 32) ? idx_lo : idx_hi;
        int r   = __shfl_sync(0xffffffffu, src, j & 31);
        float2 g = ldcg_f2(emb + (size_t)r * D_DIM + 2 * lane);
        sx += g.x; sy += g.y;
        qx += g.x * g.x; qy += g.y * g.y;
    }

    float2 h = *reinterpret_cast<const float2*>(h1 + 2 * lane);
    float part = 0.5f * (sx * sx - qx) * h.x
               + 0.5f * (sy * sy - qy) * h.y + wsum;

    #pragma unroll
    for (int o = 16; o > 0; o >>= 1)
        part += __shfl_xor_sync(0xffffffffu, part, o);

    float2 sv; sv.x = sx; sv.y = sy;
    *reinterpret_cast<float2*>(orow + 2 * lane) = sv;  // stride 66 even -> 8B aligned

    if (lane == 0) {
        if (IS_USER) {
            orow[D_DIM]     = part + bias;
            orow[D_DIM + 1] = 1.0f;
        } else {
            orow[D_DIM]     = 1.0f;
            orow[D_DIM + 1] = part;
        }
    }
}

// Interleaved roles: warp g (of 20480) handles
//   g % 5 == 0 -> user row g/5
//   else       -> item row (g/5)*4 + (g%5 - 1)
// Each 8-warp block thus carries 1-2 user warps -> near-uniform block duration,
// while keeping 256-thread blocks and full warp count (latency hiding intact).
__global__ __launch_bounds__(256)
void fm_striped_kernel(const float* __restrict__ uemb,
                       const float* __restrict__ iemb,
                       const float* __restrict__ uw,
                       const float* __restrict__ iw,
                       const float* __restrict__ gbias,
                       const float* __restrict__ h1,
                       const float* __restrict__ h2,
                       const int*   __restrict__ uidx,
                       const int*   __restrict__ iidx,
                       float*       __restrict__ out)
{
    const int lane = threadIdx.x & 31;
    const int gw   = (blockIdx.x * blockDim.x + threadIdx.x) >> 5;

    if (blockIdx.x == 0 && threadIdx.x < D_DIM) {
        out[(size_t)N_ROWS * OUT_W + threadIdx.x] = h2[threadIdx.x];
    }

    if (gw >= N_WARPS) return;

    const int u = gw / 5;
    const int r = gw - 5 * u;

    if (r == 0) {
        do_row<L_U, true>(uemb, uw, gbias[0], h1,
                          uidx + (size_t)u * L_U,
                          out + (size_t)u * OUT_W, lane);
    } else {
        const int row = 4 * u + (r - 1);
        do_row<L_I, false>(iemb, iw, 0.f, h1,
                           iidx + (size_t)row * L_I,
                           out + (size_t)(N_USERS + row) * OUT_W, lane);
    }
}

extern "C" void kernel_launch(void* const* d_in, const int* in_sizes, int n_in,
                              void* d_out, int out_size)
{
    const float* uemb  = (const float*)d_in[0];
    const float* iemb  = (const float*)d_in[1];
    const float* uw    = (const float*)d_in[2];
    const float* iw    = (const float*)d_in[3];
    const float* gbias = (const float*)d_in[4];
    const float* h1    = (const float*)d_in[5];
    const float* h2    = (const float*)d_in[6];
    const int*   uidx  = (const int*)d_in[7];
    const int*   iidx  = (const int*)d_in[8];

    float* out = (float*)d_out;

    const int threads = 256;                       // 8 warps/block
    const int blocks  = (N_WARPS * 32) / threads;  // 2560
    fm_striped_kernel<<<blocks, threads>>>(uemb, iemb, uw, iw, gbias, h1, h2,
                                           uidx, iidx, out);
}

// round 12
// speedup vs baseline: 1.1448x; 1.1389x over previous
#include <cuda_runtime.h>
#include <cstddef>

#define D_DIM   64
#define N_USERS 4096
#define N_ITEMS 16384
#define L_U     50
#define L_I     20
#define OUT_W   (D_DIM + 2)   // 66
#define N_ROWS  (N_USERS + N_ITEMS)

// One warp computes one output row. Lane l owns columns 2l, 2l+1.
// Structure identical to the best (15.1us) kernel; loads via read-only path.
template <int L, bool IS_USER>
__device__ __forceinline__
void do_row(const float* __restrict__ emb,
            const float* __restrict__ w,
            float                     bias,
            const float* __restrict__ h1,
            const int*   __restrict__ my_idx,
            float*       __restrict__ orow,
            int lane)
{
    int idx_lo = (L >= 32 || lane < L) ? __ldg(&my_idx[lane]) : 0;
    int idx_hi = 0;
    if (L > 32) idx_hi = (lane + 32 < L) ? __ldg(&my_idx[lane + 32]) : 0;

    float wsum = 0.f;
    if (L >= 32 || lane < L) wsum += __ldg(&w[idx_lo]);
    if (L > 32 && lane + 32 < L) wsum += __ldg(&w[idx_hi]);

    float sx = 0.f, sy = 0.f, qx = 0.f, qy = 0.f;

    #pragma unroll
    for (int j = 0; j < L; ++j) {
        int src = (L <= 32 || j < 32) ? idx_lo : idx_hi;
        int r   = __shfl_sync(0xffffffffu, src, j & 31);
        float2 g = __ldg(reinterpret_cast<const float2*>(
                             emb + (size_t)r * D_DIM + 2 * lane));
        sx += g.x; sy += g.y;
        qx += g.x * g.x; qy += g.y * g.y;
    }

    float2 h = __ldg(reinterpret_cast<const float2*>(h1 + 2 * lane));
    float part = 0.5f * (sx * sx - qx) * h.x
               + 0.5f * (sy * sy - qy) * h.y + wsum;

    #pragma unroll
    for (int o = 16; o > 0; o >>= 1)
        part += __shfl_xor_sync(0xffffffffu, part, o);

    float2 sv; sv.x = sx; sv.y = sy;
    *reinterpret_cast<float2*>(orow + 2 * lane) = sv;  // stride 66 even -> 8B aligned

    if (lane == 0) {
        if (IS_USER) {
            orow[D_DIM]     = part + bias;
            orow[D_DIM + 1] = 1.0f;
        } else {
            orow[D_DIM]     = 1.0f;
            orow[D_DIM + 1] = part;
        }
    }
}

__global__ __launch_bounds__(256)
void fm_fused_kernel(const float* __restrict__ uemb,
                     const float* __restrict__ iemb,
                     const float* __restrict__ uw,
                     const float* __restrict__ iw,
                     const float* __restrict__ gbias,
                     const float* __restrict__ h1,
                     const float* __restrict__ h2,
                     const int*   __restrict__ uidx,
                     const int*   __restrict__ iidx,
                     float*       __restrict__ out)
{
    const int lane = threadIdx.x & 31;
    const int gw   = (blockIdx.x * blockDim.x + threadIdx.x) >> 5;

    if (blockIdx.x == 0 && threadIdx.x < D_DIM) {
        out[(size_t)N_ROWS * OUT_W + threadIdx.x] = h2[threadIdx.x];
    }

    if (gw < N_USERS) {
        do_row<L_U, true>(uemb, uw, gbias[0], h1,
                          uidx + (size_t)gw * L_U,
                          out + (size_t)gw * OUT_W, lane);
    } else if (gw < N_ROWS) {
        const int row = gw - N_USERS;
        do_row<L_I, false>(iemb, iw, 0.f, h1,
                           iidx + (size_t)row * L_I,
                           out + (size_t)(N_USERS + row) * OUT_W, lane);
    }
}

extern "C" void kernel_launch(void* const* d_in, const int* in_sizes, int n_in,
                              void* d_out, int out_size)
{
    const float* uemb  = (const float*)d_in[0];
    const float* iemb  = (const float*)d_in[1];
    const float* uw    = (const float*)d_in[2];
    const float* iw    = (const float*)d_in[3];
    const float* gbias = (const float*)d_in[4];
    const float* h1    = (const float*)d_in[5];
    const float* h2    = (const float*)d_in[6];
    const int*   uidx  = (const int*)d_in[7];
    const int*   iidx  = (const int*)d_in[8];

    float* out = (float*)d_out;

    const int threads = 256;                 // 8 warps/block
    const int warps_per_block = threads / 32;
    const int blocks = (N_ROWS + warps_per_block - 1) / warps_per_block;  // 2560

    fm_fused_kernel<<<blocks, threads>>>(uemb, iemb, uw, iw, gbias, h1, h2,
                                         uidx, iidx, out);
}

// round 13
// speedup vs baseline: 1.2199x; 1.0655x over previous
#include <cuda_runtime.h>
#include <cstddef>

#define D_DIM   64
#define N_USERS 4096
#define N_ITEMS 16384
#define L_U     50
#define L_I     20
#define OUT_W   (D_DIM + 2)   // 66
#define N_ROWS  (N_USERS + N_ITEMS)
#define THREADS 128           // 4 warps/block: finer scheduling granularity

// One warp computes one output row. Lane l owns columns 2l, 2l+1.
// Inner body identical to the best (15.1us) kernel.
template <int L, bool IS_USER>
__device__ __forceinline__
void do_row(const float* __restrict__ emb,
            const float* __restrict__ w,
            float                     bias,
            const float* __restrict__ h1,
            const int*   __restrict__ my_idx,
            float*       __restrict__ orow,
            int lane)
{
    int idx_lo = (L >= 32 || lane < L) ? my_idx[lane] : 0;
    int idx_hi = 0;
    if (L > 32) idx_hi = (lane + 32 < L) ? my_idx[lane + 32] : 0;

    float wsum = 0.f;
    if (L >= 32 || lane < L) wsum += __ldg(&w[idx_lo]);
    if (L > 32 && lane + 32 < L) wsum += __ldg(&w[idx_hi]);

    float sx = 0.f, sy = 0.f, qx = 0.f, qy = 0.f;

    #pragma unroll
    for (int j = 0; j < L; ++j) {
        int src = (L <= 32 || j < 32) ? idx_lo : idx_hi;
        int r   = __shfl_sync(0xffffffffu, src, j & 31);
        float2 g = *reinterpret_cast<const float2*>(emb + (size_t)r * D_DIM + 2 * lane);
        sx += g.x; sy += g.y;
        qx += g.x * g.x; qy += g.y * g.y;
    }

    float2 h = *reinterpret_cast<const float2*>(h1 + 2 * lane);
    float part = 0.5f * (sx * sx - qx) * h.x
               + 0.5f * (sy * sy - qy) * h.y + wsum;

    #pragma unroll
    for (int o = 16; o > 0; o >>= 1)
        part += __shfl_xor_sync(0xffffffffu, part, o);

    float2 sv; sv.x = sx; sv.y = sy;
    *reinterpret_cast<float2*>(orow + 2 * lane) = sv;  // stride 66 even -> 8B aligned

    if (lane == 0) {
        if (IS_USER) {
            orow[D_DIM]     = part + bias;
            orow[D_DIM + 1] = 1.0f;
        } else {
            orow[D_DIM]     = 1.0f;
            orow[D_DIM + 1] = part;
        }
    }
}

__global__ __launch_bounds__(THREADS)
void fm_fused_kernel(const float* __restrict__ uemb,
                     const float* __restrict__ iemb,
                     const float* __restrict__ uw,
                     const float* __restrict__ iw,
                     const float* __restrict__ gbias,
                     const float* __restrict__ h1,
                     const float* __restrict__ h2,
                     const int*   __restrict__ uidx,
                     const int*   __restrict__ iidx,
                     float*       __restrict__ out)
{
    const int lane = threadIdx.x & 31;
    const int gw   = (blockIdx.x * blockDim.x + threadIdx.x) >> 5;

    if (blockIdx.x == 0 && threadIdx.x < D_DIM) {
        out[(size_t)N_ROWS * OUT_W + threadIdx.x] = h2[threadIdx.x];
    }

    if (gw < N_USERS) {
        do_row<L_U, true>(uemb, uw, gbias[0], h1,
                          uidx + (size_t)gw * L_U,
                          out + (size_t)gw * OUT_W, lane);
    } else if (gw < N_ROWS) {
        const int row = gw - N_USERS;
        do_row<L_I, false>(iemb, iw, 0.f, h1,
                           iidx + (size_t)row * L_I,
                           out + (size_t)(N_USERS + row) * OUT_W, lane);
    }
}

extern "C" void kernel_launch(void* const* d_in, const int* in_sizes, int n_in,
                              void* d_out, int out_size)
{
    const float* uemb  = (const float*)d_in[0];
    const float* iemb  = (const float*)d_in[1];
    const float* uw    = (const float*)d_in[2];
    const float* iw    = (const float*)d_in[3];
    const float* gbias = (const float*)d_in[4];
    const float* h1    = (const float*)d_in[5];
    const float* h2    = (const float*)d_in[6];
    const int*   uidx  = (const int*)d_in[7];
    const int*   iidx  = (const int*)d_in[8];

    float* out = (float*)d_out;

    const int warps_per_block = THREADS / 32;                              // 4
    const int blocks = (N_ROWS + warps_per_block - 1) / warps_per_block;   // 5120

    fm_fused_kernel<<<blocks, THREADS>>>(uemb, iemb, uw, iw, gbias, h1, h2,
                                         uidx, iidx, out);
}